// round 8
// baseline (speedup 1.0000x reference)
#include <cuda_runtime.h>

#define FP      80
#define MTAPS   24
#define NSTAGES 20
#define BATCH   8
#define NFRAMES 1024
#define TLEN    (NFRAMES * FP)        // 81920

#define RPT     8                     // 8 | 80 -> thread never crosses a frame
#define BLOCK   352                   // 11 warps; 2 blocks/SM
#define WINW    (BLOCK * RPT)         // 2816
#define HALO    (NSTAGES * MTAPS)     // 480
#define TBOUT   (WINW - HALO)         // 2336 (multiple of 16 -> alignment holds)
#define PADZ    24
#define BPB     ((TLEN + TBOUT - 1) / TBOUT)   // 36 -> grid 288 = 2 per SM, one wave

typedef unsigned long long u64p;

__device__ __forceinline__ u64p pk2(float lo, float hi) {
    u64p r; asm("mov.b64 %0, {%1, %2};" : "=l"(r) : "f"(lo), "f"(hi)); return r;
}
__device__ __forceinline__ void upk2(u64p v, float& lo, float& hi) {
    asm("mov.b64 {%0, %1}, %2;" : "=f"(lo), "=f"(hi) : "l"(v));
}
__device__ __forceinline__ u64p ffma2(u64p a, u64p b, u64p c) {
    u64p d; asm("fma.rn.f32x2 %0, %1, %2, %3;" : "=l"(d) : "l"(a), "l"(b), "l"(c)); return d;
}
__device__ __forceinline__ u64p dup2(float v) { return pk2(v, v); }

__global__ void __launch_bounds__(BLOCK, 2)
fir_taylor_kernel(const float* __restrict__ x,
                  const float* __restrict__ mc,
                  const float* __restrict__ a,
                  const float* __restrict__ wts,
                  float* __restrict__ out)
{
    __shared__ float buf0[WINW + PADZ];
    __shared__ float buf1[WINW + PADZ];
    __shared__ float s_f[NSTAGES + 1];   // a[i] * prod_{k<=i} wts[k]

    const int tid = threadIdx.x;
    const int blk = blockIdx.x;
    const int b   = blk / BPB;
    const int tb  = blk % BPB;
    const int t0  = tb * TBOUT;
    const int g0  = t0 - HALO;

    if (tid == 0) {
        float P = 1.0f;
        s_f[0] = a[0];
        for (int i = 1; i <= NSTAGES; i++) { P *= wts[i]; s_f[i] = a[i] * P; }
    }
    if (tid < PADZ) { buf0[tid] = 0.0f; buf1[tid] = 0.0f; }

    const int lp    = tid * RPT;
    const int tbase = g0 + lp;

    // own 8 samples -> regs + smem
    const float* xb = x + b * TLEN;
    float acc[RPT];
#pragma unroll
    for (int r = 0; r < RPT; r++) {
        int t = tbase + r;
        acc[r] = (t >= 0 && t < TLEN) ? __ldg(xb + t) : 0.0f;
    }
    {
        float4* st = (float4*)(buf0 + PADZ + lp);
        float4 f0; f0.x = acc[0]; f0.y = acc[1]; f0.z = acc[2]; f0.w = acc[3];
        float4 f1; f1.x = acc[4]; f1.y = acc[5]; f1.z = acc[6]; f1.w = acc[7];
        st[0] = f0; st[1] = f1;
    }

    // ---- stage-invariant packed coefficients kj = (cc_j, dp_j) ----
    int tc = tbase < 0 ? 0 : (tbase >= TLEN ? TLEN - 1 : tbase);
    int n  = tc / FP;
    int n1 = (n + 1 < NFRAMES) ? n + 1 : NFRAMES - 1;
    const float invP = 1.0f / (float)FP;
    const float w0   = (float)(tc - n * FP) * invP;

    const float* mrow0 = mc + ((long)b * NFRAMES + n)  * (MTAPS + 1);
    const float* mrow1 = mc + ((long)b * NFRAMES + n1) * (MTAPS + 1);

    u64p kj[MTAPS];
#pragma unroll
    for (int j = 0; j < MTAPS; j++) {
        float c0v = mrow0[j + 1];
        float d   = mrow1[j + 1] - c0v;
        kj[j] = pk2(fmaf(w0, d, c0v), d * invP);
    }
    const float k0 = mrow0[0];
    const float dk = mrow1[0] - k0;

    __syncthreads();

    float y[RPT];
    {
        const float f0 = s_f[0];
#pragma unroll
        for (int r = 0; r < RPT; r++) y[r] = acc[r] * f0;
    }

    float* cur = buf0;
    float* nxt = buf1;

#pragma unroll 1
    for (int i = 1; i <= NSTAGES; i++) {
        const float fi = s_f[i];

        // halo w[0..23] = cur[lp-24 .. lp-1]
        float w[MTAPS];
        {
            const float4* v = (const float4*)(cur + PADZ + lp - MTAPS);
#pragma unroll
            for (int q = 0; q < MTAPS / 4; q++) {
                float4 f = v[q];
                w[4*q+0] = f.x; w[4*q+1] = f.y; w[4*q+2] = f.z; w[4*q+3] = f.w;
            }
        }

        float na[RPT];

        // ---- group A: outputs r = 0..3 (window w[24..27] = acc[0..3])
        {
            u64p ab0 = 0ULL, ab1 = 0ULL, ab2 = 0ULL, ab3 = 0ULL;
            u64p d0 = dup2(w[23]);
            u64p d1 = dup2(acc[0]);
            u64p d2 = dup2(acc[1]);
            u64p d3 = dup2(acc[2]);
#pragma unroll
            for (int j = 1; j <= MTAPS; j++) {
                u64p k = kj[j - 1];
                ab0 = ffma2(d0, k, ab0);
                ab1 = ffma2(d1, k, ab1);
                ab2 = ffma2(d2, k, ab2);
                ab3 = ffma2(d3, k, ab3);
                d3 = d2; d2 = d1; d1 = d0;
                if (j < MTAPS) d0 = dup2(w[23 - j]);
            }
            float A, B;
            upk2(ab0, A, B); na[0] = A;
            upk2(ab1, A, B); na[1] = fmaf(1.0f, B, A);
            upk2(ab2, A, B); na[2] = fmaf(2.0f, B, A);
            upk2(ab3, A, B); na[3] = fmaf(3.0f, B, A);
        }

        // ---- group B: outputs r = 4..7 (window base 28)
        {
            u64p ab0 = 0ULL, ab1 = 0ULL, ab2 = 0ULL, ab3 = 0ULL;
            u64p d0 = dup2(acc[3]);   // idx 27
            u64p d1 = dup2(acc[4]);
            u64p d2 = dup2(acc[5]);
            u64p d3 = dup2(acc[6]);
#pragma unroll
            for (int j = 1; j <= MTAPS; j++) {
                u64p k = kj[j - 1];
                ab0 = ffma2(d0, k, ab0);
                ab1 = ffma2(d1, k, ab1);
                ab2 = ffma2(d2, k, ab2);
                ab3 = ffma2(d3, k, ab3);
                d3 = d2; d2 = d1; d1 = d0;
                if (j < MTAPS) {
                    int idx = 27 - j;
                    d0 = (idx >= 24) ? dup2(acc[idx - 24]) : dup2(w[idx]);
                }
            }
            float A, B;
            upk2(ab0, A, B); na[4] = fmaf(4.0f, B, A);
            upk2(ab1, A, B); na[5] = fmaf(5.0f, B, A);
            upk2(ab2, A, B); na[6] = fmaf(6.0f, B, A);
            upk2(ab3, A, B); na[7] = fmaf(7.0f, B, A);
        }

#pragma unroll
        for (int r = 0; r < RPT; r++) {
            acc[r] = na[r];
            y[r]   = fmaf(na[r], fi, y[r]);
        }

        if (i < NSTAGES) {
            float4* st = (float4*)(nxt + PADZ + lp);
            float4 f0; f0.x = acc[0]; f0.y = acc[1]; f0.z = acc[2]; f0.w = acc[3];
            float4 f1; f1.x = acc[4]; f1.y = acc[5]; f1.z = acc[6]; f1.w = acc[7];
            st[0] = f0; st[1] = f1;
            __syncthreads();
            float* tmp = cur; cur = nxt; nxt = tmp;
        }
    }

    // ---- epilogue: out = y * exp(interp(mc[...,0])) ----
    if (lp >= HALO) {
        float* ob = out + b * TLEN;
#pragma unroll
        for (int r = 0; r < RPT; r++) {
            int tt = tbase + r;
            if (tt < TLEN) {
                float K = expf(fmaf(fmaf((float)r, invP, w0), dk, k0));
                ob[tt] = y[r] * K;
            }
        }
    }
}

extern "C" void kernel_launch(void* const* d_in, const int* in_sizes, int n_in,
                              void* d_out, int out_size)
{
    (void)in_sizes; (void)n_in; (void)out_size;
    const float* x   = (const float*)d_in[0];
    const float* mc  = (const float*)d_in[1];
    const float* a   = (const float*)d_in[2];
    const float* wts = (const float*)d_in[3];
    float* out = (float*)d_out;

    fir_taylor_kernel<<<BATCH * BPB, BLOCK>>>(x, mc, a, wts, out);
}